// round 6
// baseline (speedup 1.0000x reference)
#include <cuda_runtime.h>

#define NUM_CODES 1024
#define TPB 128          // threads per block == rows per block
#define RS  68           // padded row stride in floats (272 B): conflict-free LDS/STS.128
#define HPAD 5           // each hist bin on its own 128B line (stride 32 ints)

__device__ int g_hist[NUM_CODES << HPAD];   // zero at load
__device__ unsigned int g_done;             // zero at load

// ---------------------------------------------------------------------------
// Single fused kernel. Block = 128 threads = 128 rows.
// cp.async rows into shared (coalesced, L2-only), compute 4 centered codes
// per row, regenerate outputs on the fly during the coalesced stage-out.
// Last block computes perplexity/utilization and resets global state.
// ---------------------------------------------------------------------------
__global__ __launch_bounds__(TPB, 6) void fsq_main(
    const float* __restrict__ ze,    // (B, 64)
    const float* __restrict__ Win,   // (4, 64) row-major
    const float4* __restrict__ Wout4,// (64) float4 rows
    float* __restrict__ zq,          // (B, 64)
    float* __restrict__ idx_out,     // (B,)
    float* __restrict__ scal,        // 4 scalars
    float invB)
{
    __shared__ float  tile[TPB * RS];    // 34816 B input tile
    __shared__ float  sWin[256];         // 4 x 64
    __shared__ float4 sC[TPB];           // 4 centered codes per row (2 KB)
    __shared__ bool   isLast;
    __shared__ float  red[8];

    const int t = threadIdx.x;
    #pragma unroll
    for (int i = t; i < 256; i += TPB) sWin[i] = Win[i];

    const unsigned int rowBase = (unsigned int)blockIdx.x * TPB;

    // ---- stage in: 128 rows x 16 float4 via cp.async.cg (L2-only) ----
    const float4* gin = reinterpret_cast<const float4*>(ze) + (size_t)rowBase * 16;
    #pragma unroll
    for (int i = 0; i < 16; i++) {
        int f = t + i * TPB;            // float4 index within tile
        int r = f >> 4, c = f & 15;
        unsigned int dst = (unsigned int)__cvta_generic_to_shared(&tile[r * RS + c * 4]);
        asm volatile("cp.async.cg.shared.global [%0], [%1], 16;\n"
                     :: "r"(dst), "l"(gin + f) : "memory");
    }
    asm volatile("cp.async.commit_group;\n" ::: "memory");
    asm volatile("cp.async.wait_group 0;\n" ::: "memory");
    __syncthreads();

    // ---- compute: thread t owns row t ----
    {
        const float4* zr = reinterpret_cast<const float4*>(&tile[t * RS]);
        const float4* w0 = reinterpret_cast<const float4*>(sWin);
        const float4* w1 = reinterpret_cast<const float4*>(sWin + 64);
        const float4* w2 = reinterpret_cast<const float4*>(sWin + 128);
        const float4* w3 = reinterpret_cast<const float4*>(sWin + 192);

        float a0 = 0.f, a1 = 0.f, a2 = 0.f, a3 = 0.f;
        #pragma unroll
        for (int k = 0; k < 16; k++) {
            float4 v  = zr[k];
            float4 x0 = w0[k], x1 = w1[k], x2 = w2[k], x3 = w3[k];
            a0 = fmaf(v.x, x0.x, fmaf(v.y, x0.y, fmaf(v.z, x0.z, fmaf(v.w, x0.w, a0))));
            a1 = fmaf(v.x, x1.x, fmaf(v.y, x1.y, fmaf(v.z, x1.z, fmaf(v.w, x1.w, a1))));
            a2 = fmaf(v.x, x2.x, fmaf(v.y, x2.y, fmaf(v.z, x2.z, fmaf(v.w, x2.w, a2))));
            a3 = fmaf(v.x, x3.x, fmaf(v.y, x3.y, fmaf(v.z, x3.z, fmaf(v.w, x3.w, a3))));
        }

        // FSQ quantize: levels (8,8,8,2), strides (1,8,64,512)
        const float acc[4] = {a0, a1, a2, a3};
        const float Lm1[4] = {7.f, 7.f, 7.f, 1.f};
        const int   str[4] = {1, 8, 64, 512};
        float c[4];
        int index = 0;
        #pragma unroll
        for (int j = 0; j < 4; j++) {
            float u = (tanhf(acc[j]) + 1.0f) * 0.5f;
            float s = u * Lm1[j];
            float r = rintf(s);                       // round-half-even == jnp.round
            r = fminf(fmaxf(r, 0.0f), Lm1[j]);
            index += (int)r * str[j];
            c[j] = r - Lm1[j] * 0.5f;
        }

        __stcs(&idx_out[rowBase + t], (float)index);  // coalesced streaming STG.32
        atomicAdd(&g_hist[index << HPAD], 1);         // 1 bin per 128B line

        sC[t] = make_float4(c[0], c[1], c[2], c[3]);  // 16B per row
    }
    __syncthreads();

    // ---- stage out: regenerate outputs, fully coalesced, streaming ----
    // f = t + i*TPB: column group f&15 == t&15 (constant), row r = f>>4 varies.
    // W_out rows loaded HERE so their 16 regs are not live through compute.
    {
        const int cgrp = t & 15;
        const float4 q0 = Wout4[4 * cgrp + 0];
        const float4 q1 = Wout4[4 * cgrp + 1];
        const float4 q2 = Wout4[4 * cgrp + 2];
        const float4 q3 = Wout4[4 * cgrp + 3];

        float4* gout = reinterpret_cast<float4*>(zq) + (size_t)rowBase * 16;
        #pragma unroll
        for (int i = 0; i < 16; i++) {
            int f = t + i * TPB;
            int r = f >> 4;
            float4 cr = sC[r];                 // broadcast LDS.128 (2 rows per warp)
            float4 o;
            o.x = fmaf(cr.x, q0.x, fmaf(cr.y, q0.y, fmaf(cr.z, q0.z, cr.w * q0.w)));
            o.y = fmaf(cr.x, q1.x, fmaf(cr.y, q1.y, fmaf(cr.z, q1.z, cr.w * q1.w)));
            o.z = fmaf(cr.x, q2.x, fmaf(cr.y, q2.y, fmaf(cr.z, q2.z, cr.w * q2.w)));
            o.w = fmaf(cr.x, q3.x, fmaf(cr.y, q3.y, fmaf(cr.z, q3.z, cr.w * q3.w)));
            __stcs(&gout[f], o);
        }
    }

    // ---- last-block finalize (fused; no second launch) ----
    __threadfence();
    if (t == 0) {
        unsigned int v = atomicAdd(&g_done, 1u);
        isLast = (v == gridDim.x - 1);
    }
    __syncthreads();
    if (!isLast) return;

    __threadfence();   // acquire: all blocks' hist atomics visible
    float term = 0.f, nz = 0.f;
    #pragma unroll
    for (int i = t; i < NUM_CODES; i += TPB) {
        int cnt = g_hist[i << HPAD];
        g_hist[i << HPAD] = 0;                        // reset for next replay
        float p = (float)cnt * invB;
        term += p * logf(p + 1e-10f);
        nz   += (cnt > 0) ? 1.0f : 0.0f;
    }
    #pragma unroll
    for (int o = 16; o > 0; o >>= 1) {
        term += __shfl_down_sync(0xFFFFFFFFu, term, o);
        nz   += __shfl_down_sync(0xFFFFFFFFu, nz, o);
    }
    if ((t & 31) == 0) { red[t >> 5] = term; red[4 + (t >> 5)] = nz; }
    __syncthreads();
    if (t == 0) {
        float s = red[0] + red[1] + red[2] + red[3];
        float n = red[4] + red[5] + red[6] + red[7];
        scal[0] = 0.0f;                  // commitment_loss
        scal[1] = 0.0f;                  // codebook_loss
        scal[2] = expf(-s);              // perplexity
        scal[3] = n * (1.0f / 1024.0f);  // utilization
        g_done = 0;                      // reset for next replay
    }
}

// ---------------------------------------------------------------------------
extern "C" void kernel_launch(void* const* d_in, const int* in_sizes, int n_in,
                              void* d_out, int out_size) {
    const float* ze   = (const float*)d_in[0];  // (B, 64)
    const float* Win  = (const float*)d_in[1];  // (4, 64)
    const float* Wout = (const float*)d_in[2];  // (64, 4)

    const int B = in_sizes[0] / 64;
    float* out  = (float*)d_out;
    float* zq   = out;                       // B*64
    float* idxf = out + (size_t)B * 64;      // B
    float* scal = idxf + B;                  // 4 scalars

    const int grid = B / TPB;                // 524288 / 128 = 4096

    fsq_main<<<grid, TPB>>>(ze, Win, (const float4*)Wout,
                            zq, idxf, scal, 1.0f / (float)B);
}